// round 16
// baseline (speedup 1.0000x reference)
#include <cuda_runtime.h>

#define BB 4
#define SS 512
#define HH 128

typedef unsigned long long u64;

__device__ __forceinline__ void ffma2(u64 &acc, u64 a, u64 b) {
    asm("fma.rn.f32x2 %0, %1, %2, %0;" : "+l"(acc) : "l"(a), "l"(b));
}
__device__ __forceinline__ u64 addf2(u64 a, u64 b) {
    u64 r; asm("add.rn.f32x2 %0, %1, %2;" : "=l"(r) : "l"(a), "l"(b)); return r;
}
__device__ __forceinline__ u64 pk2(float v) {   // {v, v}
    u64 r; asm("mov.b64 %0, {%1, %2};" : "=l"(r) : "f"(v), "f"(v)); return r;
}
__device__ __forceinline__ float2 upk(u64 v) {
    float2 r; asm("mov.b64 {%0, %1}, %2;" : "=f"(r.x), "=f"(r.y) : "l"(v)); return r;
}

// 592 blocks (148/batch = exactly 4/SM, one balanced wave) x 128 threads.
// Thread (hq = tid&31, q = tid>>5) owns h-quad {4hq..4hq+3}, k-quarter q (32 k).
// Mainloop in packed f32x2: 28 FFMA2 (=56 FMA) + 5 LDS.128 + 3 LDG.128 per iter.
// Weights pipelined one iteration ahead. Warp w finishes output row w.
__global__ __launch_bounds__(128, 4) void align_kernel(
    const float* __restrict__ x, const float* __restrict__ ref,
    const float* __restrict__ Wa, const float* __restrict__ Wb,
    const float* __restrict__ b1, const float* __restrict__ W2,
    const float* __restrict__ b2, const float* __restrict__ Wp1,
    const float* __restrict__ bp1, const float* __restrict__ Wp2,
    const float* __restrict__ bp2, float* __restrict__ out)
{
    const int tid = threadIdx.x;
    const int q   = tid >> 5;        // k-quarter 0..3 (= warp id)
    const int hq  = tid & 31;        // h-quad (h = 4hq .. 4hq+3)

    const int b   = blockIdx.x / 148;
    const int ib  = blockIdx.x - b * 148;
    int t0, cnt;
    if (ib < 68) { t0 = ib * 4;               cnt = 4; }
    else         { t0 = 272 + (ib - 68) * 3;  cnt = 3; }

    // rowsd[k][0..4] = {x,x} rows t0-1..t0+3 ; [5..9] = {ref,ref}. 80B stride (16B-aligned).
    __shared__ __align__(16) u64 rowsd[HH][10];
    __shared__ u64 part[4][28][32];     // packed partials from all 4 quarters

    // ---- stage rows duplicated: thread tid owns k = tid ----
    {
        const int k = tid;
        #pragma unroll
        for (int r = 0; r < 5; r++) {
            int t  = t0 - 1 + r;
            int tc = t < 0 ? 0 : (t > SS - 1 ? SS - 1 : t);
            const size_t gi = (size_t)(b * SS + tc) * HH + k;
            rowsd[k][r]     = pk2(x[gi]);
            rowsd[k][5 + r] = pk2(ref[gi]);
        }
    }
    __syncthreads();

    // ---- packed accumulators: [r][jp], jp=0 -> h{4hq,4hq+1}, jp=1 -> h{4hq+2,4hq+3} ----
    u64 A2[5][2], C2[5][2], P2[4][2];
    {
        ulonglong2 ab = make_ulonglong2(0ULL, 0ULL), pb = make_ulonglong2(0ULL, 0ULL);
        if (q == 0) {
            ab = ((const ulonglong2*)b1)[hq];
            pb = ((const ulonglong2*)bp1)[hq];
        }
        #pragma unroll
        for (int r = 0; r < 5; r++) {
            A2[r][0] = ab.x; A2[r][1] = ab.y;
            C2[r][0] = 0ULL; C2[r][1] = 0ULL;
        }
        #pragma unroll
        for (int r = 0; r < 4; r++) { P2[r][0] = pb.x; P2[r][1] = pb.y; }
    }

    const ulonglong2* __restrict__ Wa2 = (const ulonglong2*)Wa;   // [k*32 + hq]
    const ulonglong2* __restrict__ Wb2 = (const ulonglong2*)Wb;
    const ulonglong2* __restrict__ Wp2_ = (const ulonglong2*)Wp1;

    const int kb = q * 32;

    // ---- prologue: weights for first iteration ----
    ulonglong2 wa_c = Wa2[kb * 32 + hq];
    ulonglong2 wb_c = Wb2[kb * 32 + hq];
    ulonglong2 wp_c = Wp2_[kb * 32 + hq];

    #pragma unroll 2
    for (int kk = 0; kk < 31; kk++) {
        const int k = kb + kk;
        // prefetch next iteration's weights
        ulonglong2 wa_n = Wa2[(k + 1) * 32 + hq];
        ulonglong2 wb_n = Wb2[(k + 1) * 32 + hq];
        ulonglong2 wp_n = Wp2_[(k + 1) * 32 + hq];

        const ulonglong2 d01 = *(const ulonglong2*)&rowsd[k][0];  // x0 x1
        const ulonglong2 d23 = *(const ulonglong2*)&rowsd[k][2];  // x2 x3
        const ulonglong2 d45 = *(const ulonglong2*)&rowsd[k][4];  // x4 r0
        const ulonglong2 d67 = *(const ulonglong2*)&rowsd[k][6];  // r1 r2
        const ulonglong2 d89 = *(const ulonglong2*)&rowsd[k][8];  // r3 r4
        const u64 xd[5] = {d01.x, d01.y, d23.x, d23.y, d45.x};
        const u64 rd[5] = {d45.y, d67.x, d67.y, d89.x, d89.y};

        #pragma unroll
        for (int r = 0; r < 5; r++) {
            ffma2(A2[r][0], xd[r], wa_c.x);  ffma2(A2[r][1], xd[r], wa_c.y);
            ffma2(C2[r][0], rd[r], wb_c.x);  ffma2(C2[r][1], rd[r], wb_c.y);
        }
        #pragma unroll
        for (int r = 0; r < 4; r++) {
            ffma2(P2[r][0], xd[r + 1], wp_c.x);  ffma2(P2[r][1], xd[r + 1], wp_c.y);
        }

        wa_c = wa_n; wb_c = wb_n; wp_c = wp_n;
    }
    // ---- epilogue iteration (kk = 31) ----
    {
        const int k = kb + 31;
        const ulonglong2 d01 = *(const ulonglong2*)&rowsd[k][0];
        const ulonglong2 d23 = *(const ulonglong2*)&rowsd[k][2];
        const ulonglong2 d45 = *(const ulonglong2*)&rowsd[k][4];
        const ulonglong2 d67 = *(const ulonglong2*)&rowsd[k][6];
        const ulonglong2 d89 = *(const ulonglong2*)&rowsd[k][8];
        const u64 xd[5] = {d01.x, d01.y, d23.x, d23.y, d45.x};
        const u64 rd[5] = {d45.y, d67.x, d67.y, d89.x, d89.y};
        #pragma unroll
        for (int r = 0; r < 5; r++) {
            ffma2(A2[r][0], xd[r], wa_c.x);  ffma2(A2[r][1], xd[r], wa_c.y);
            ffma2(C2[r][0], rd[r], wb_c.x);  ffma2(C2[r][1], rd[r], wb_c.y);
        }
        #pragma unroll
        for (int r = 0; r < 4; r++) {
            ffma2(P2[r][0], xd[r + 1], wp_c.x);  ffma2(P2[r][1], xd[r + 1], wp_c.y);
        }
    }

    // ---- ALL quarters publish packed partials: A d=0..9, C d=10..19, P d=20..27 ----
    #pragma unroll
    for (int r = 0; r < 5; r++) {
        part[q][r * 2 + 0][hq]      = A2[r][0];
        part[q][r * 2 + 1][hq]      = A2[r][1];
        part[q][10 + r * 2 + 0][hq] = C2[r][0];
        part[q][10 + r * 2 + 1][hq] = C2[r][1];
    }
    #pragma unroll
    for (int r = 0; r < 4; r++) {
        part[q][20 + r * 2 + 0][hq] = P2[r][0];
        part[q][20 + r * 2 + 1][hq] = P2[r][1];
    }
    __syncthreads();

    // ---- parallel tail: warp w finishes output row i = w ----
    const int i = q;
    if (i < cnt) {
        const int t = t0 + i;

        float a0[4], a1[4], c0[4], c1[4], pw[4];
        #pragma unroll
        for (int jp = 0; jp < 2; jp++) {
            const int dA0 = i * 2 + jp;          // row i   (= t-1)
            const int dA1 = (i + 1) * 2 + jp;    // row i+1 (= t)
            const u64 sA0 = addf2(addf2(part[0][dA0][hq], part[1][dA0][hq]),
                                  addf2(part[2][dA0][hq], part[3][dA0][hq]));
            const u64 sA1 = addf2(addf2(part[0][dA1][hq], part[1][dA1][hq]),
                                  addf2(part[2][dA1][hq], part[3][dA1][hq]));
            const u64 sC0 = addf2(addf2(part[0][10 + dA0][hq], part[1][10 + dA0][hq]),
                                  addf2(part[2][10 + dA0][hq], part[3][10 + dA0][hq]));
            const u64 sC1 = addf2(addf2(part[0][10 + dA1][hq], part[1][10 + dA1][hq]),
                                  addf2(part[2][10 + dA1][hq], part[3][10 + dA1][hq]));
            const int dP = 20 + i * 2 + jp;
            const u64 sP  = addf2(addf2(part[0][dP][hq], part[1][dP][hq]),
                                  addf2(part[2][dP][hq], part[3][dP][hq]));
            const float2 uA0 = upk(sA0), uA1 = upk(sA1);
            const float2 uC0 = upk(sC0), uC1 = upk(sC1);
            const float2 uP  = upk(sP);
            a0[2 * jp] = uA0.x; a0[2 * jp + 1] = uA0.y;
            a1[2 * jp] = uA1.x; a1[2 * jp + 1] = uA1.y;
            c0[2 * jp] = uC0.x; c0[2 * jp + 1] = uC0.y;
            c1[2 * jp] = uC1.x; c1[2 * jp + 1] = uC1.y;
            pw[2 * jp] = fmaxf(uP.x, 0.f); pw[2 * jp + 1] = fmaxf(uP.y, 0.f);
        }

        const float4 w2v = ((const float4*)W2)[hq];
        const float  w2a[4] = {w2v.x, w2v.y, w2v.z, w2v.w};
        const float4* wpq = (const float4*)&Wp2[12 * hq];
        const float4 q0v = wpq[0], q1v = wpq[1], q2v = wpq[2];
        const float wq[12] = {q0v.x, q0v.y, q0v.z, q0v.w,
                              q1v.x, q1v.y, q1v.z, q1v.w,
                              q2v.x, q2v.y, q2v.z, q2v.w};

        float v[6] = {0.f, 0.f, 0.f, 0.f, 0.f, 0.f};
        #pragma unroll
        for (int j = 0; j < 4; j++) {
            v[0] += fmaxf(a1[j] + c1[j], 0.f) * w2a[j];  // A[t,t]
            v[1] += fmaxf(a0[j] + c1[j], 0.f) * w2a[j];  // A[t-1,t]  (insert)
            v[2] += fmaxf(a1[j] + c0[j], 0.f) * w2a[j];  // A[t,t-1]  (delete)
            v[3] += pw[j] * wq[3 * j + 0];
            v[4] += pw[j] * wq[3 * j + 1];
            v[5] += pw[j] * wq[3 * j + 2];
        }
        #pragma unroll
        for (int j = 0; j < 6; j++) {
            float s = v[j];
            s += __shfl_xor_sync(0xffffffffu, s, 16);
            s += __shfl_xor_sync(0xffffffffu, s, 8);
            s += __shfl_xor_sync(0xffffffffu, s, 4);
            s += __shfl_xor_sync(0xffffffffu, s, 2);
            s += __shfl_xor_sync(0xffffffffu, s, 1);
            v[j] = s;   // all lanes hold the full sum
        }

        // decision, computed redundantly on all 32 lanes
        int   op    = -1;    // -1 => copy x (t == 0)
        float alpha = 0.f;
        const float b2s = b2[0];
        const float Ad  = 1.0f / (1.0f + expf(-(v[0] + b2s)));
        if (t != 0) {
            const float Ai   = 1.0f / (1.0f + expf(-(v[1] + b2s)));
            const float Adel = 1.0f / (1.0f + expf(-(v[2] + b2s)));
            const float l0 = v[3] + bp2[0];
            const float l1 = v[4] + bp2[1];
            const float l2 = v[5] + bp2[2];
            const float mx  = fmaxf(l0, fmaxf(l1, l2));
            const float lse = mx + logf(expf(l0 - mx) + expf(l1 - mx) + expf(l2 - mx));
            const float m   = Ad   * (l0 - lse);
            const float ins = Ai   * (l1 - lse);
            const float del = Adel * (l2 - lse);
            if (m >= ins && m >= del) op = 0;   // first-max tie-break == jnp.argmax
            else if (ins >= del)      op = 1;
            else                      op = 2;
            alpha = Ad;
        }

        // blend inputs via coalesced float4 LDG (L1-hot)
        const int tm1 = (t > 0) ? (t - 1) : 0;
        const float4 cx4 = *(const float4*)&x[(size_t)(b * SS + t) * HH + 4 * hq];
        const float4 cr4 = *(const float4*)&ref[(size_t)(b * SS + t) * HH + 4 * hq];
        const float4 px4 = *(const float4*)&x[(size_t)(b * SS + tm1) * HH + 4 * hq];

        float4 o;
        if (op < 0) {
            o = cx4;
        } else if (op == 0) {
            o.x = (1.f - alpha) * cx4.x + alpha * cr4.x;
            o.y = (1.f - alpha) * cx4.y + alpha * cr4.y;
            o.z = (1.f - alpha) * cx4.z + alpha * cr4.z;
            o.w = (1.f - alpha) * cx4.w + alpha * cr4.w;
        } else if (op == 1) {
            o = cr4;
        } else {
            o = px4;
        }
        *(float4*)&out[(size_t)(b * SS + t) * HH + 4 * hq] = o;
    }
}

extern "C" void kernel_launch(void* const* d_in, const int* in_sizes, int n_in,
                              void* d_out, int out_size) {
    const float* x   = (const float*)d_in[0];
    const float* ref = (const float*)d_in[1];
    const float* Wa  = (const float*)d_in[2];
    const float* Wb  = (const float*)d_in[3];
    const float* b1  = (const float*)d_in[4];
    const float* W2  = (const float*)d_in[5];
    const float* b2  = (const float*)d_in[6];
    const float* Wp1 = (const float*)d_in[7];
    const float* bp1 = (const float*)d_in[8];
    const float* Wp2 = (const float*)d_in[9];
    const float* bp2 = (const float*)d_in[10];

    dim3 grid(BB * 148);      // 592 blocks: 148 per batch, 4 per SM, one wave
    dim3 block(128);          // 32 h-quads x 4 k-quarters
    align_kernel<<<grid, block>>>(x, ref, Wa, Wb, b1, W2, b2,
                                  Wp1, bp1, Wp2, bp2, (float*)d_out);
}